// round 2
// baseline (speedup 1.0000x reference)
#include <cuda_runtime.h>

// cost = where(0<=v<=1, A*exp(B*(1+v)) + C, OOB_COST), v = X[i*8+7]
// A=0.01, B=4.81, C=0.0, OOB=3.0

__global__ __launch_bounds__(256)
void penalizer_kernel(const float* __restrict__ X,
                      float* __restrict__ out,
                      int n) {
    int i = (blockIdx.x * blockDim.x + threadIdx.x) * 4;
    if (i + 3 < n) {
        // 4 independent strided loads (one 32B sector each) — MLP=4
        float v0 = __ldg(X + (size_t)(i + 0) * 8 + 7);
        float v1 = __ldg(X + (size_t)(i + 1) * 8 + 7);
        float v2 = __ldg(X + (size_t)(i + 2) * 8 + 7);
        float v3 = __ldg(X + (size_t)(i + 3) * 8 + 7);

        float4 r;
        {
            float c = 0.01f * __expf(4.81f * (1.0f + v0));
            r.x = (v0 >= 0.0f && v0 <= 1.0f) ? c : 3.0f;
        }
        {
            float c = 0.01f * __expf(4.81f * (1.0f + v1));
            r.y = (v1 >= 0.0f && v1 <= 1.0f) ? c : 3.0f;
        }
        {
            float c = 0.01f * __expf(4.81f * (1.0f + v2));
            r.z = (v2 >= 0.0f && v2 <= 1.0f) ? c : 3.0f;
        }
        {
            float c = 0.01f * __expf(4.81f * (1.0f + v3));
            r.w = (v3 >= 0.0f && v3 <= 1.0f) ? c : 3.0f;
        }
        *reinterpret_cast<float4*>(out + i) = r;
    } else if (i < n) {
        for (int j = i; j < n; ++j) {
            float v = __ldg(X + (size_t)j * 8 + 7);
            float c = 0.01f * __expf(4.81f * (1.0f + v));
            out[j] = (v >= 0.0f && v <= 1.0f) ? c : 3.0f;
        }
    }
}

extern "C" void kernel_launch(void* const* d_in, const int* in_sizes, int n_in,
                              void* d_out, int out_size) {
    const float* X = (const float*)d_in[0];
    float* out = (float*)d_out;
    int n = out_size;  // one output per row; in_sizes[0] == n*8

    int threads = 256;
    int rows_per_block = threads * 4;
    int blocks = (n + rows_per_block - 1) / rows_per_block;
    penalizer_kernel<<<blocks, threads>>>(X, out, n);
}

// round 3
// speedup vs baseline: 1.0383x; 1.0383x over previous
#include <cuda_runtime.h>

// cost = where(0<=v<=1, A*exp(B*(1+v)) + C, OOB_COST), v = X[i*8+7]
// A=0.01, B=4.81, C=0.0, OOB=3.0
// Pure streaming: every 32B row = 1 DRAM sector, all sectors needed.
// 8 rows/thread: MLP_p1=8 front-batched evict-first loads, 2x STG.128 streaming stores.

__device__ __forceinline__ float penalize(float v) {
    float c = 0.01f * __expf(4.81f * (1.0f + v));
    return (v >= 0.0f && v <= 1.0f) ? c : 3.0f;
}

__global__ __launch_bounds__(256)
void penalizer_kernel(const float* __restrict__ X,
                      float* __restrict__ out,
                      int n) {
    int i = (blockIdx.x * blockDim.x + threadIdx.x) * 8;
    if (i + 7 < n) {
        const float* p = X + (size_t)i * 8 + 7;
        // 8 independent evict-first loads, one 32B sector each (MLP=8)
        float v0 = __ldcs(p + 0 * 8);
        float v1 = __ldcs(p + 1 * 8);
        float v2 = __ldcs(p + 2 * 8);
        float v3 = __ldcs(p + 3 * 8);
        float v4 = __ldcs(p + 4 * 8);
        float v5 = __ldcs(p + 5 * 8);
        float v6 = __ldcs(p + 6 * 8);
        float v7 = __ldcs(p + 7 * 8);

        float4 r0, r1;
        r0.x = penalize(v0);
        r0.y = penalize(v1);
        r0.z = penalize(v2);
        r0.w = penalize(v3);
        r1.x = penalize(v4);
        r1.y = penalize(v5);
        r1.z = penalize(v6);
        r1.w = penalize(v7);

        __stcs(reinterpret_cast<float4*>(out + i), r0);
        __stcs(reinterpret_cast<float4*>(out + i + 4), r1);
    } else if (i < n) {
        for (int j = i; j < n; ++j) {
            float v = __ldcs(X + (size_t)j * 8 + 7);
            out[j] = penalize(v);
        }
    }
}

extern "C" void kernel_launch(void* const* d_in, const int* in_sizes, int n_in,
                              void* d_out, int out_size) {
    const float* X = (const float*)d_in[0];
    float* out = (float*)d_out;
    int n = out_size;  // one output per row; in_sizes[0] == n*8

    int threads = 256;
    int rows_per_block = threads * 8;
    int blocks = (n + rows_per_block - 1) / rows_per_block;
    penalizer_kernel<<<blocks, threads>>>(X, out, n);
}